// round 1
// baseline (speedup 1.0000x reference)
#include <cuda_runtime.h>
#include <cstdint>
#include <math.h>

// Problem constants
#define NB    1024      // entities
#define ND    256       // embedding dim
#define NV    50000     // candidate vocab
#define NC    64        // candidates per side
#define NTOPK 10

// ---------------- scratch (device globals; no allocation allowed) ----------
__device__ __align__(16) float g_words [2048 * ND];   // rows 0..1023 = wl, 1024..2047 = wr
__device__ __align__(16) float g_align [2048 * ND];
__device__ __align__(16) float g_aggre [2048 * ND];   // rows 0..1023 = aggre_l, 1024.. = aggre_r
__device__ __align__(16) float g_concat[NB * 2 * ND];
__device__ __align__(16) float g_phrase[NB * ND];
__device__ float g_rowmax[NB];
__device__ float g_rowsum[NB];

// ---------------- f32x2 helpers (Blackwell packed fp32 FMA) ----------------
__device__ __forceinline__ void fma_f32x2(unsigned long long &d,
                                          unsigned long long a,
                                          unsigned long long b) {
    asm("fma.rn.f32x2 %0, %1, %2, %0;" : "+l"(d) : "l"(a), "l"(b));
}
__device__ __forceinline__ unsigned long long dup_f32(float a) {
    unsigned int u = __float_as_uint(a);
    unsigned long long r;
    asm("mov.b64 %0, {%1, %1};" : "=l"(r) : "r"(u));
    return r;
}
__device__ __forceinline__ float2 unpack_f32x2(unsigned long long v) {
    float2 f;
    f.x = __uint_as_float((unsigned int)(v & 0xffffffffull));
    f.y = __uint_as_float((unsigned int)(v >> 32));
    return f;
}

// ---------------- kernel 1: gather word embeddings --------------------------
__global__ void k_gather_words(const int* __restrict__ wl,
                               const int* __restrict__ wr,
                               const float* __restrict__ wemb) {
    int idx = blockIdx.x * 256 + threadIdx.x;       // 2048*64 float4's
    int r = idx >> 6, q = idx & 63;
    int id = (r < NB) ? wl[r] : wr[r - NB];
    const float4* src = reinterpret_cast<const float4*>(wemb);
    float4* dst = reinterpret_cast<float4*>(g_words);
    dst[(size_t)r * 64 + q] = src[(size_t)id * 64 + q];
}

// ---------------- generic tiled GEMM with f32x2 accumulation ----------------
// C[M,N] = A[M,K] @ op(B);  TRANSB: B is [N,K] row-major (use B^T).
// DOEPI: C = tanh(C + bias[n]).
// BM=BN=128, BK=16, 256 threads, 8x8 per thread (paired along N).
template<int TRANSB, int DOEPI>
__global__ void k_gemm(const float* __restrict__ A, const float* __restrict__ Bm,
                       const float* __restrict__ bias, float* __restrict__ Cc,
                       int M, int N, int K) {
    const int BM = 128, BN = 128, BK = 16;
    __shared__ __align__(16) float As[BK][BM];
    __shared__ __align__(16) float Bs[BK][BN];
    int tid = threadIdx.x;
    int tx = tid & 15, ty = tid >> 4;
    int m0 = blockIdx.y * BM;
    int n0 = blockIdx.x * BN;

    unsigned long long acc[8][4];
    #pragma unroll
    for (int i = 0; i < 8; i++)
        #pragma unroll
        for (int j = 0; j < 4; j++) acc[i][j] = 0ull;

    for (int k0 = 0; k0 < K; k0 += BK) {
        // A tile (transpose-store): 128 rows x 16 k
        #pragma unroll
        for (int p = 0; p < 2; p++) {
            int f = tid + p * 256;
            int row = f >> 2, kv = f & 3;
            float4 v = *reinterpret_cast<const float4*>(
                A + (size_t)(m0 + row) * K + k0 + kv * 4);
            As[kv * 4 + 0][row] = v.x;
            As[kv * 4 + 1][row] = v.y;
            As[kv * 4 + 2][row] = v.z;
            As[kv * 4 + 3][row] = v.w;
        }
        // B tile
        if (TRANSB) {
            #pragma unroll
            for (int p = 0; p < 2; p++) {
                int f = tid + p * 256;
                int row = f >> 2, kv = f & 3;      // row = n index
                float4 v = make_float4(0.f, 0.f, 0.f, 0.f);
                if (n0 + row < N)
                    v = *reinterpret_cast<const float4*>(
                        Bm + (size_t)(n0 + row) * K + k0 + kv * 4);
                Bs[kv * 4 + 0][row] = v.x;
                Bs[kv * 4 + 1][row] = v.y;
                Bs[kv * 4 + 2][row] = v.z;
                Bs[kv * 4 + 3][row] = v.w;
            }
        } else {
            #pragma unroll
            for (int p = 0; p < 2; p++) {
                int f = tid + p * 256;
                int kk = f >> 5, nv = f & 31;
                float4 v = *reinterpret_cast<const float4*>(
                    Bm + (size_t)(k0 + kk) * N + n0 + nv * 4);
                *reinterpret_cast<float4*>(&Bs[kk][nv * 4]) = v;
            }
        }
        __syncthreads();

        #pragma unroll
        for (int k = 0; k < BK; k++) {
            const float4* ap = reinterpret_cast<const float4*>(&As[k][ty * 8]);
            float4 a0 = ap[0], a1 = ap[1];
            const ulonglong2* bp = reinterpret_cast<const ulonglong2*>(&Bs[k][tx * 8]);
            ulonglong2 b01 = bp[0], b23 = bp[1];
            float af[8] = {a0.x, a0.y, a0.z, a0.w, a1.x, a1.y, a1.z, a1.w};
            unsigned long long bf[4] = {b01.x, b01.y, b23.x, b23.y};
            #pragma unroll
            for (int i = 0; i < 8; i++) {
                unsigned long long ad = dup_f32(af[i]);
                #pragma unroll
                for (int j = 0; j < 4; j++) fma_f32x2(acc[i][j], ad, bf[j]);
            }
        }
        __syncthreads();
    }

    // epilogue
    #pragma unroll
    for (int i = 0; i < 8; i++) {
        size_t m = (size_t)(m0 + ty * 8 + i);
        float* crow = Cc + m * (size_t)N;
        #pragma unroll
        for (int j = 0; j < 4; j++) {
            int n = n0 + tx * 8 + j * 2;
            float2 r = unpack_f32x2(acc[i][j]);
            if (DOEPI) {
                r.x = tanhf(r.x + bias[n]);
                r.y = tanhf(r.y + bias[n + 1]);
            }
            if (n + 1 < N) {
                *reinterpret_cast<float2*>(crow + n) = r;
            } else if (n < N) {
                crow[n] = r.x;
            }
        }
    }
}

// ---------------- kernel 3: attention (per entity, per side) ---------------
// side 0: aggre_l = attend(align(wl), cand_r);  side 1: aggre_r = attend(align(wr), cand_l)
__global__ void k_attend(const int* __restrict__ cand_l,
                         const int* __restrict__ cand_r,
                         const float* __restrict__ cemb) {
    int b = blockIdx.x, side = blockIdx.y;
    int t = threadIdx.x, w = t >> 5, l = t & 31;
    const int* ids = (side == 0) ? (cand_r + b * NC) : (cand_l + b * NC);
    int arow = side * NB + b;

    __shared__ float al[ND];
    __shared__ int ids_sm[NC];
    __shared__ float sc[NC];
    __shared__ float att[NC];

    al[t] = g_align[(size_t)arow * ND + t];
    if (t < NC) ids_sm[t] = ids[t];
    __syncthreads();

    // scores: warp w handles candidates w*8 .. w*8+7
    #pragma unroll
    for (int ci = 0; ci < 8; ci++) {
        int c = w * 8 + ci;
        const float* e = cemb + (size_t)ids_sm[c] * ND;
        float p = 0.f;
        #pragma unroll
        for (int j = 0; j < 8; j++) {
            int d = l + 32 * j;
            p += e[d] * al[d];
        }
        #pragma unroll
        for (int o = 16; o > 0; o >>= 1) p += __shfl_down_sync(0xffffffffu, p, o);
        if (l == 0) sc[c] = p;
    }
    __syncthreads();

    // softmax over 64 (warp 0)
    if (t < 32) {
        float s0 = sc[t], s1 = sc[t + 32];
        float mx = fmaxf(s0, s1);
        #pragma unroll
        for (int o = 16; o > 0; o >>= 1) mx = fmaxf(mx, __shfl_xor_sync(0xffffffffu, mx, o));
        float e0 = expf(s0 - mx), e1 = expf(s1 - mx);
        float sum = e0 + e1;
        #pragma unroll
        for (int o = 16; o > 0; o >>= 1) sum += __shfl_xor_sync(0xffffffffu, sum, o);
        att[t] = e0 / sum;
        att[t + 32] = e1 / sum;
    }
    __syncthreads();

    // weighted sum
    float accd = 0.f;
    #pragma unroll 8
    for (int c = 0; c < NC; c++)
        accd += att[c] * __ldg(cemb + (size_t)ids_sm[c] * ND + t);
    g_aggre[(size_t)arow * ND + t] = accd;
}

// ---------------- kernel 4: build concat [words_whole | cands_whole] -------
__global__ void k_concat() {
    int f = blockIdx.x * 256 + threadIdx.x;  // 1024*128 float4's
    int b = f >> 7, q = f & 127;
    const float4* W4 = reinterpret_cast<const float4*>(g_words);
    const float4* A4 = reinterpret_cast<const float4*>(g_aggre);
    float4* C4 = reinterpret_cast<float4*>(g_concat);
    float4 x, y;
    if (q < 64) {
        x = W4[(size_t)b * 64 + q];
        y = W4[(size_t)(NB + b) * 64 + q];
    } else {
        int qq = q - 64;
        x = A4[(size_t)b * 64 + qq];
        y = A4[(size_t)(NB + b) * 64 + qq];
    }
    float4 r;
    r.x = x.x + y.x; r.y = x.y + y.y; r.z = x.z + y.z; r.w = x.w + y.w;
    C4[(size_t)b * 128 + q] = r;
}

// ---------------- kernel 6: per-row softmax stats + exact top-10 -----------
__global__ void k_softmax_topk(const float* __restrict__ logits,
                               float* __restrict__ out_idx) {
    int b = blockIdx.x, t = threadIdx.x;
    const float* row = logits + (size_t)b * NV;

    float m = -INFINITY, s = 0.f;
    float tv[NTOPK];
    int ti[NTOPK];
    #pragma unroll
    for (int q = 0; q < NTOPK; q++) { tv[q] = -INFINITY; ti[q] = 0x7fffffff; }

    for (int v = t; v < NV; v += 256) {
        float x = row[v];
        if (x > m) { s = s * expf(m - x) + 1.0f; m = x; }
        else       { s += expf(x - m); }
        if (x > tv[NTOPK - 1]) {
            float nv = x; int ni = v;
            #pragma unroll
            for (int q = 0; q < NTOPK; q++) {
                if (nv > tv[q]) {
                    float fv = tv[q]; tv[q] = nv; nv = fv;
                    int ii = ti[q]; ti[q] = ni; ni = ii;
                }
            }
        }
    }

    // block merge of (max, sum)
    __shared__ float smv[256], sms[256];
    smv[t] = m; sms[t] = s;
    __syncthreads();
    for (int st = 128; st > 0; st >>= 1) {
        if (t < st) {
            float m1 = smv[t], s1 = sms[t];
            float m2 = smv[t + st], s2 = sms[t + st];
            float mm = fmaxf(m1, m2);
            sms[t] = s1 * expf(m1 - mm) + s2 * expf(m2 - mm);
            smv[t] = mm;
        }
        __syncthreads();
    }
    if (t == 0) { g_rowmax[b] = smv[0]; g_rowsum[b] = sms[0]; }

    // iterative extraction of global top-10 (tie -> lower index, matching jax)
    __shared__ float rv[256];
    __shared__ int ri[256];
    for (int r10 = 0; r10 < NTOPK; r10++) {
        rv[t] = tv[0]; ri[t] = ti[0];
        __syncthreads();
        for (int st = 128; st > 0; st >>= 1) {
            if (t < st) {
                float v2 = rv[t + st]; int i2 = ri[t + st];
                if (v2 > rv[t] || (v2 == rv[t] && i2 < ri[t])) { rv[t] = v2; ri[t] = i2; }
            }
            __syncthreads();
        }
        float bv = rv[0]; int bi = ri[0];
        if (t == 0) out_idx[(size_t)b * NTOPK + r10] = (float)bi;
        if (tv[0] == bv && ti[0] == bi) {
            #pragma unroll
            for (int q = 0; q < NTOPK - 1; q++) { tv[q] = tv[q + 1]; ti[q] = ti[q + 1]; }
            tv[NTOPK - 1] = -INFINITY; ti[NTOPK - 1] = 0x7fffffff;
        }
        __syncthreads();
    }
}

// ---------------- kernel 7: y_pred = exp(x - m) / s (in place) -------------
__global__ void k_ypred(float* __restrict__ d) {
    int b = blockIdx.y;
    int v = blockIdx.x * 256 + threadIdx.x;
    if (v < NV) {
        size_t o = (size_t)b * NV + v;
        float x = d[o];
        d[o] = expf(x - g_rowmax[b]) / g_rowsum[b];
    }
}

// ---------------- host launcher ---------------------------------------------
extern "C" void kernel_launch(void* const* d_in, const int* in_sizes, int n_in,
                              void* d_out, int out_size) {
    const int*   wl_ids = (const int*)  d_in[0];
    const int*   wr_ids = (const int*)  d_in[1];
    const int*   cl_ids = (const int*)  d_in[2];
    const int*   cr_ids = (const int*)  d_in[3];
    const float* wemb   = (const float*)d_in[4];
    const float* cemb   = (const float*)d_in[5];
    const float* W_a    = (const float*)d_in[6];
    const float* b_a    = (const float*)d_in[7];
    const float* W_c    = (const float*)d_in[8];
    const float* b_c    = (const float*)d_in[9];
    float* out = (float*)d_out;

    float* g_words_p;  cudaGetSymbolAddress((void**)&g_words_p,  g_words);
    float* g_align_p;  cudaGetSymbolAddress((void**)&g_align_p,  g_align);
    float* g_concat_p; cudaGetSymbolAddress((void**)&g_concat_p, g_concat);
    float* g_phrase_p; cudaGetSymbolAddress((void**)&g_phrase_p, g_phrase);

    // 1) gather wl/wr
    k_gather_words<<<512, 256>>>(wl_ids, wr_ids, wemb);

    // 2) align = tanh(words @ W_a + b_a)   [2048 x 256]
    k_gemm<0, 1><<<dim3(2, 16), 256>>>(g_words_p, W_a, b_a, g_align_p,
                                       2048, ND, ND);

    // 3) attention (both sides)
    k_attend<<<dim3(NB, 2), 256>>>(cl_ids, cr_ids, cemb);

    // 4) concat [words_whole | cands_whole]
    k_concat<<<512, 256>>>();

    // 5) phrase = tanh(concat @ W_c + b_c)  [1024 x 256], K=512
    k_gemm<0, 1><<<dim3(2, 8), 256>>>(g_concat_p, W_c, b_c, g_phrase_p,
                                      NB, ND, 2 * ND);

    // 6) logits = phrase @ cand_emb^T  [1024 x 50000]  -> d_out (scratch)
    k_gemm<1, 0><<<dim3((NV + 127) / 128, NB / 128), 256>>>(
        g_phrase_p, cemb, nullptr, out, NB, NV, ND);

    // 7) softmax stats + top-10 indices -> tail of d_out
    k_softmax_topk<<<NB, 256>>>(out, out + (size_t)NB * NV);

    // 8) y_pred in place
    k_ypred<<<dim3((NV + 255) / 256, NB), 256>>>(out);
}